// round 17
// baseline (speedup 1.0000x reference)
#include <cuda_runtime.h>
#include <cuda_fp16.h>
#include <cstdint>
#include <math.h>

// Problem constants
#define CB   16
#define CT   2048
#define CC   512
#define CH   4
#define CDH  128
#define NTOK (CB * CT)     // 32768 tokens
#define NROW (NTOK * 2)    // 65536 token-device rows

// GEMM tiling: 128x128 tile, BK=64, single fp16 product, 3-stage pipeline
#define BM 128
#define BN 128
#define BK 64
#define STAGE 32768u
#define SMEM_G 98304             // 3 stages * 32K (>= epi 128*132*4 = 67584)

#define SW128(off) ((off) ^ (((off) >> 3) & 0x70))

// ---------------------------------------------------------------------------
// Scratch (static __device__; no runtime allocation)
// ---------------------------------------------------------------------------
__device__ __half g_XE [(size_t)NROW * CC];           // fp16 activations
__device__ __half g_QKV[(size_t)NROW * 3 * CC];       // fp16 q|k|v
__device__ __half g_CTX[(size_t)NROW * CC];           // viewed as (NTOK, 1024)
__device__ float  g_PATT[(size_t)NTOK * 4];
__device__ __half g_W1h[3 * CC * CC];
// fused-weight pipeline
__device__ float  g_PART[16 * CC * CC];               // split-K partials
__device__ float  g_S1[CC * CC];                      // W2a @ Wp
__device__ float  g_S2[CC * CC];                      // W2b @ Wi
__device__ __half g_Uh[CC * 2 * CC];                  // fp16([S1@Wo | S2@Wo])
__device__ float  g_BB[2 * CC];
__device__ float  g_BT[CC];

// ---------------------------------------------------------------------------
// Helpers
// ---------------------------------------------------------------------------
__device__ __forceinline__ uint32_t smem_u32(const void* p) {
    uint32_t a;
    asm("{ .reg .u64 t; cvta.to.shared.u64 t, %1; cvt.u32.u64 %0, t; }" : "=r"(a) : "l"(p));
    return a;
}
__device__ __forceinline__ void cp16(uint32_t dst, const void* src) {
    unsigned long long g = (unsigned long long)__cvta_generic_to_global(src);
    asm volatile("cp.async.cg.shared.global [%0], [%1], 16;" :: "r"(dst), "l"(g) : "memory");
}
__device__ __forceinline__ void cp_commit() { asm volatile("cp.async.commit_group;" ::: "memory"); }
__device__ __forceinline__ void cp_wait2()  { asm volatile("cp.async.wait_group 2;" ::: "memory"); }
__device__ __forceinline__ void cp_wait1()  { asm volatile("cp.async.wait_group 1;" ::: "memory"); }
__device__ __forceinline__ void cp_wait0()  { asm volatile("cp.async.wait_group 0;" ::: "memory"); }

__device__ __forceinline__ void ldsm4(uint32_t* r, uint32_t addr) {
    asm volatile("ldmatrix.sync.aligned.m8n8.x4.shared.b16 {%0,%1,%2,%3}, [%4];"
                 : "=r"(r[0]), "=r"(r[1]), "=r"(r[2]), "=r"(r[3]) : "r"(addr));
}
__device__ __forceinline__ void mma16816(float* d, const uint32_t* a, const uint32_t* b) {
    asm volatile(
        "mma.sync.aligned.m16n8k16.row.col.f32.f16.f16.f32 "
        "{%0,%1,%2,%3}, {%4,%5,%6,%7}, {%8,%9}, {%0,%1,%2,%3};"
        : "+f"(d[0]), "+f"(d[1]), "+f"(d[2]), "+f"(d[3])
        : "r"(a[0]), "r"(a[1]), "r"(a[2]), "r"(a[3]), "r"(b[0]), "r"(b[1]));
}
__device__ __forceinline__ float4 ld_half4(const __half* p) {
    __half2 a = *(const __half2*)p;
    __half2 b = *(const __half2*)(p + 2);
    float2 fa = __half22float2(a), fb = __half22float2(b);
    return make_float4(fa.x, fa.y, fb.x, fb.y);
}

// ---------------------------------------------------------------------------
// Split-K fp32 SGEMM body (64x64 tile, 256 threads, 4x4 per thread).
// One K-slice of one product; partials to g_PART[slice]. Caller supplies smem.
// ---------------------------------------------------------------------------
__device__ void snn_body(float (*As)[68], float (*Bs)[68],
                         const float* __restrict__ A, int lda,
                         const float* __restrict__ B, int ldb,
                         int n_blk, int m_blk, int kz, int slice, int tid) {
    int n0 = n_blk * 64, m0 = m_blk * 64, k0 = kz * 64;
    int tr = tid / 16, tc = tid % 16;
    int lr = tid / 16, lc4 = (tid % 16) * 4;

    #pragma unroll
    for (int h = 0; h < 4; h++) {
        int r = lr + h * 16;
        float4 a = *(const float4*)(A + (size_t)(m0 + r) * lda + k0 + lc4);
        As[lc4 + 0][r] = a.x; As[lc4 + 1][r] = a.y;
        As[lc4 + 2][r] = a.z; As[lc4 + 3][r] = a.w;
        *(float4*)&Bs[r][lc4] = *(const float4*)(B + (size_t)(k0 + r) * ldb + n0 + lc4);
    }
    __syncthreads();

    float acc[4][4];
    #pragma unroll
    for (int i = 0; i < 4; i++)
        #pragma unroll
        for (int j = 0; j < 4; j++) acc[i][j] = 0.f;

    #pragma unroll 8
    for (int k = 0; k < 64; k++) {
        float4 ra = *(const float4*)&As[k][tr * 4];
        float4 rb = *(const float4*)&Bs[k][tc * 4];
        float a[4] = {ra.x, ra.y, ra.z, ra.w};
        float b[4] = {rb.x, rb.y, rb.z, rb.w};
        #pragma unroll
        for (int i = 0; i < 4; i++)
            #pragma unroll
            for (int j = 0; j < 4; j++)
                acc[i][j] += a[i] * b[j];
    }

    float* part = g_PART + (size_t)slice * CC * CC;
    #pragma unroll
    for (int i = 0; i < 4; i++)
        *(float4*)(part + (size_t)(m0 + tr * 4 + i) * CC + n0 + tc * 4) =
            make_float4(acc[i][0], acc[i][1], acc[i][2], acc[i][3]);
}

// ---------------------------------------------------------------------------
// K1: fused pre-stage. Grid (64, 16, 37), threads (32, 8).
//   z <  32 : embed/transpose x -> XE fp16
//   z == 32 : snn stage1 (W2a@Wp, W2b@Wi partials), 1024 blocks
//   z 33-35 : w1 -> fp16 convert (3*CC*CC elems)
//   z == 36 : bias1 fold (2 blocks active)
// ---------------------------------------------------------------------------
__global__ void __launch_bounds__(256)
k_embed_pre(const float* __restrict__ x, const float* __restrict__ emb,
            const float* __restrict__ w1,
            const float* __restrict__ w2,
            const float* __restrict__ wp, const float* __restrict__ bp,
            const float* __restrict__ wim, const float* __restrict__ bim,
            const float* __restrict__ bo) {
    __shared__ __align__(16) float As[64][68];
    __shared__ __align__(16) float Bs[64][68];
    int tid = threadIdx.y * 32 + threadIdx.x;
    int z = blockIdx.z;
    int flat = blockIdx.y * 64 + blockIdx.x;

    if (z < 32) {
        // embed: 32x32 transpose tile per (b, d)
        float (*s)[33] = (float(*)[33])As;   // reuse smem
        int t0 = blockIdx.x * 32;
        int c0 = blockIdx.y * 32;
        int b = z >> 1, d = z & 1;
        #pragma unroll
        for (int j = 0; j < 4; j++) {
            int c = c0 + threadIdx.y + j * 8;
            s[threadIdx.y + j * 8][threadIdx.x] =
                x[(((size_t)b * CC + c) * 2 + d) * CT + t0 + threadIdx.x];
        }
        __syncthreads();
        #pragma unroll
        for (int j = 0; j < 4; j++) {
            int t = t0 + threadIdx.y + j * 8;
            int c = c0 + threadIdx.x;
            float v = s[threadIdx.x][threadIdx.y + j * 8] + emb[d * CC + c];
            g_XE[((size_t)(b * CT + t) * 2 + d) * CC + c] = __float2half(v);
        }
    } else if (z == 32) {
        // snn stage1: flat in [0,1024): n_blk(3b) | m_blk(3b) | z16(4b)
        int n_blk = flat & 7, m_blk = (flat >> 3) & 7, z16 = flat >> 6;
        int p = z16 >> 3, kz = z16 & 7;
        if (p == 0) snn_body(As, Bs, w2,      2 * CC, wp,  CC, n_blk, m_blk, kz, z16, tid);
        else        snn_body(As, Bs, w2 + CC, 2 * CC, wim, CC, n_blk, m_blk, kz, z16, tid);
    } else if (z <= 35) {
        int i = ((z - 33) * 1024 + flat) * 256 + tid;
        g_W1h[i] = __float2half(w1[i]);    // 3*CC*CC = 3072*256 exactly
    } else {
        if (flat < 2) {
            int i = flat * 256 + tid;
            float s0 = bp[i], s1 = bim[i];
            for (int k = 0; k < CC; k++) {
                float b = bo[k];
                s0 += wp[i * CC + k] * b;
                s1 += wim[i * CC + k] * b;
            }
            g_BB[i] = s0;
            g_BB[CC + i] = s1;
        }
    }
}

// ---------------------------------------------------------------------------
// HMMA GEMM, single fp16 product, 3-stage cp.async pipeline.
// D[m][n] = bias[n] + sum_k A[m][k]*B[n][k]
// MODE 2: fp32 transposed (B, C, T).  MODE 3: fp16 row-major.
// SRED1 (GEMM1 only): blocks with blockIdx.y == gridDim.y-1 reduce
// stage-1 partials into S1/S2 instead of doing GEMM work.
// ---------------------------------------------------------------------------
__device__ __forceinline__ void load_chunk(
    uint32_t sbase,
    const __half* __restrict__ A, int lda, int m0,
    const __half* __restrict__ Bh, int ldw, int n0, int kc, int tid)
{
    #pragma unroll
    for (int t = 0; t < 4; t++) {
        int id = tid + t * 256;
        int r = id >> 3, j = id & 7;
        uint32_t off = SW128((uint32_t)(r * 128 + j * 16));
        size_t ga = (size_t)(m0 + r) * lda + (size_t)kc * BK + j * 8;
        cp16(sbase + off, A + ga);
        size_t gb = (size_t)(n0 + r) * ldw + (size_t)kc * BK + j * 8;
        cp16(sbase + 16384 + off, Bh + gb);
    }
    cp_commit();
}

template <int MODE, int NCHUNK, bool SRED1>
__global__ void __launch_bounds__(256, 2)
k_tgemm(const __half* __restrict__ A, int lda,
        const __half* __restrict__ Bh, int ldw,
        const float* __restrict__ bias,
        float* __restrict__ of, __half* __restrict__ oh, int ldc)
{
    extern __shared__ __align__(1024) char smem[];
    int tid = threadIdx.x;

    if (SRED1 && blockIdx.y == gridDim.y - 1) {
        // reduce stage-1 partials: slices p*8..p*8+7 -> S1/S2 (fixed order)
        const int total = 2 * CC * CC;
        const int stride = gridDim.x * 256;
        for (int idx = blockIdx.x * 256 + tid; idx < total; idx += stride) {
            int p = idx >> 18, r = idx & (CC * CC - 1);
            const float* base = g_PART + (size_t)p * 8 * CC * CC;
            float s = 0.f;
            #pragma unroll
            for (int sl = 0; sl < 8; sl++)
                s += base[(size_t)sl * CC * CC + r];
            (p ? g_S2 : g_S1)[r] = s;
        }
        return;
    }

    uint32_t sb = smem_u32(smem);
    int lane = tid & 31, wid = tid >> 5;
    int m0 = blockIdx.y * BM, n0 = blockIdx.x * BN;
    int wm = (wid >> 2) * 64, wn = (wid & 3) * 32;

    float acc[4][4][4];
    #pragma unroll
    for (int a = 0; a < 4; a++)
        #pragma unroll
        for (int b = 0; b < 4; b++)
            #pragma unroll
            for (int c = 0; c < 4; c++) acc[a][b][c] = 0.f;

    uint32_t axor   = (uint32_t)(lane & 7) << 4;
    uint32_t arow   = (uint32_t)(wm + (lane & 15)) * 128;
    uint32_t achunk = (uint32_t)(lane >> 4) * 16;
    uint32_t brow   = (uint32_t)(wn + (lane & 7) + ((lane >> 4) << 3)) * 128;
    uint32_t bchunk = (uint32_t)((lane >> 3) & 1) * 16;

    load_chunk(sb,             A, lda, m0, Bh, ldw, n0, 0, tid);
    if (NCHUNK > 1) load_chunk(sb + STAGE,     A, lda, m0, Bh, ldw, n0, 1, tid);
    if (NCHUNK > 2) load_chunk(sb + 2 * STAGE, A, lda, m0, Bh, ldw, n0, 2, tid);

    for (int i = 0; i < NCHUNK; i++) {
        if (i + 2 < NCHUNK) cp_wait2();
        else if (i + 1 < NCHUNK) cp_wait1();
        else cp_wait0();
        __syncthreads();
        uint32_t st = sb + (uint32_t)(i % 3) * STAGE;

        #pragma unroll
        for (int ks = 0; ks < 4; ks++) {
            uint32_t act = ((uint32_t)(ks * 32) + achunk) ^ axor;
            uint32_t bct = ((uint32_t)(ks * 32) + bchunk) ^ axor;
            uint32_t ah[4][4], bh[2][4];
            #pragma unroll
            for (int mi = 0; mi < 4; mi++)
                ldsm4(ah[mi], st + arow + (uint32_t)mi * 2048 + act);
            #pragma unroll
            for (int nj = 0; nj < 2; nj++)
                ldsm4(bh[nj], st + 16384 + brow + (uint32_t)nj * 2048 + bct);
            #pragma unroll
            for (int mi = 0; mi < 4; mi++)
                #pragma unroll
                for (int ni = 0; ni < 4; ni++)
                    mma16816(acc[mi][ni], ah[mi], &bh[ni >> 1][(ni & 1) * 2]);
        }
        __syncthreads();
        if (i + 3 < NCHUNK)
            load_chunk(sb + (uint32_t)(i % 3) * STAGE,
                       A, lda, m0, Bh, ldw, n0, i + 3, tid);
    }

    // epilogue: frags -> padded smem (+bias) -> coalesced stores
    float* epi = (float*)smem;
    int g = lane >> 2, t2 = (lane & 3) * 2;
    #pragma unroll
    for (int mi = 0; mi < 4; mi++) {
        #pragma unroll
        for (int ni = 0; ni < 4; ni++) {
            int r = wm + mi * 16 + g;
            int c = wn + ni * 8 + t2;
            float b0 = bias[n0 + c], b1 = bias[n0 + c + 1];
            epi[r * 132 + c]           = acc[mi][ni][0] + b0;
            epi[r * 132 + c + 1]       = acc[mi][ni][1] + b1;
            epi[(r + 8) * 132 + c]     = acc[mi][ni][2] + b0;
            epi[(r + 8) * 132 + c + 1] = acc[mi][ni][3] + b1;
        }
    }
    __syncthreads();

    if (MODE == 2) {
        int b = m0 >> 11, tb = m0 & (CT - 1);
        #pragma unroll 4
        for (int idx = tid; idx < BM * BN; idx += 256) {
            int n = idx >> 7, tt = idx & 127;
            of[(size_t)b * (CC * CT) + (size_t)(n0 + n) * CT + tb + tt] = epi[tt * 132 + n];
        }
    } else {  // MODE 3: fp16 row-major, half2 stores
        #pragma unroll 4
        for (int idx = tid; idx < BM * BN / 2; idx += 256) {
            int r = idx / (BN / 2), c = (idx % (BN / 2)) * 2;
            __half2 v = __floats2half2_rn(epi[r * 132 + c], epi[r * 132 + c + 1]);
            *(__half2*)(oh + (size_t)(m0 + r) * ldc + n0 + c) = v;
        }
    }
}

// ---------------------------------------------------------------------------
// K3: tiny 2x2 attention + piggybacked snn stage2.
// Blocks [0, NTOK/2): attention.  Blocks [NTOK/2, NTOK/2+1024): S@Wo partials.
// ---------------------------------------------------------------------------
__global__ void __launch_bounds__(256)
k_attn(const float* __restrict__ wo) {
    __shared__ __align__(16) float As[64][68];
    __shared__ __align__(16) float Bs[64][68];
    int tid = threadIdx.x;

    if (blockIdx.x >= NTOK / 2) {
        int flat = blockIdx.x - NTOK / 2;   // [0, 1024)
        int n_blk = flat & 7, m_blk = (flat >> 3) & 7, z16 = flat >> 6;
        int p = z16 >> 3, kz = z16 & 7;
        snn_body(As, Bs, p ? g_S2 : g_S1, CC, wo, CC, n_blk, m_blk, kz, z16, tid);
        return;
    }

    float (*sp)[CH][4] = (float(*)[CH][4])As;  // reuse smem
    int local = tid >> 7;
    int token = blockIdx.x * 2 + local;
    int head = (tid >> 5) & 3;
    int lane = tid & 31;

    const __half* base0 = g_QKV + (size_t)(2 * token) * (3 * CC);
    const __half* base1 = base0 + 3 * CC;
    int col4 = head * CDH + lane * 4;

    float4 q0 = ld_half4(base0 + col4);
    float4 k0 = ld_half4(base0 + CC + col4);
    float4 v0 = ld_half4(base0 + 2 * CC + col4);
    float4 q1 = ld_half4(base1 + col4);
    float4 k1 = ld_half4(base1 + CC + col4);
    float4 v1 = ld_half4(base1 + 2 * CC + col4);

    float s00 = q0.x * k0.x + q0.y * k0.y + q0.z * k0.z + q0.w * k0.w;
    float s01 = q0.x * k1.x + q0.y * k1.y + q0.z * k1.z + q0.w * k1.w;
    float s10 = q1.x * k0.x + q1.y * k0.y + q1.z * k0.z + q1.w * k0.w;
    float s11 = q1.x * k1.x + q1.y * k1.y + q1.z * k1.z + q1.w * k1.w;

    #pragma unroll
    for (int o = 16; o > 0; o >>= 1) {
        s00 += __shfl_xor_sync(0xffffffffu, s00, o);
        s01 += __shfl_xor_sync(0xffffffffu, s01, o);
        s10 += __shfl_xor_sync(0xffffffffu, s10, o);
        s11 += __shfl_xor_sync(0xffffffffu, s11, o);
    }
    const float sc = 0.088388347648318447f;  // 1/sqrt(128)
    s00 *= sc; s01 *= sc; s10 *= sc; s11 *= sc;

    float mx0 = fmaxf(s00, s01);
    float e00 = expf(s00 - mx0), e01 = expf(s01 - mx0);
    float inv0 = 1.f / (e00 + e01);
    float p00 = e00 * inv0, p01 = e01 * inv0;

    float mx1 = fmaxf(s10, s11);
    float e10 = expf(s10 - mx1), e11 = expf(s11 - mx1);
    float inv1 = 1.f / (e10 + e11);
    float p10 = e10 * inv1, p11 = e11 * inv1;

    size_t row0 = (size_t)(2 * token) * CC;
    __half2* d00 = (__half2*)(g_CTX + row0 + col4);
    __half2* d10 = (__half2*)(g_CTX + row0 + CC + col4);
    d00[0] = __floats2half2_rn(p00 * v0.x + p01 * v1.x, p00 * v0.y + p01 * v1.y);
    d00[1] = __floats2half2_rn(p00 * v0.z + p01 * v1.z, p00 * v0.w + p01 * v1.w);
    d10[0] = __floats2half2_rn(p10 * v0.x + p11 * v1.x, p10 * v0.y + p11 * v1.y);
    d10[1] = __floats2half2_rn(p10 * v0.z + p11 * v1.z, p10 * v0.w + p11 * v1.w);

    if (lane == 0) {
        sp[local][head][0] = p00; sp[local][head][1] = p01;
        sp[local][head][2] = p10; sp[local][head][3] = p11;
    }
    __syncthreads();
    if ((tid & 127) < 4) {
        int j = tid & 3;
        float s = (sp[local][0][j] + sp[local][1][j]) +
                  (sp[local][2][j] + sp[local][3][j]);
        g_PATT[(size_t)token * 4 + j] = s * 0.25f;
    }
}

// ---------------------------------------------------------------------------
// K4: finish preamble — reduce stage-2 partials straight to Uh; bias2.
// Grid 2050: blocks [0,2048) handle Uh, [2048,2050) handle bias2.
// ---------------------------------------------------------------------------
__global__ void __launch_bounds__(256)
k_finish(const float* __restrict__ w2, const float* __restrict__ b2) {
    int tid = threadIdx.x;
    if (blockIdx.x < 2048) {
        int idx = blockIdx.x * 256 + tid;        // [0, 524288)
        int p = idx >> 18, rem = idx & (CC * CC - 1);
        int m = rem >> 9, n = rem & 511;
        const float* base = g_PART + (size_t)p * 8 * CC * CC;
        float s = 0.f;
        #pragma unroll
        for (int sl = 0; sl < 8; sl++)
            s += base[(size_t)sl * CC * CC + rem];
        g_Uh[(size_t)m * (2 * CC) + p * CC + n] = __float2half(s);
    } else {
        int i = (blockIdx.x - 2048) * 256 + tid;  // [0, 512)
        float s = b2[i];
        for (int a = 0; a < CC; a++)
            s += w2[i * 2 * CC + a] * g_BB[a] + w2[i * 2 * CC + CC + a] * g_BB[CC + a];
        g_BT[i] = s;
    }
}

// ---------------------------------------------------------------------------
// K6: avg_attention tail
// ---------------------------------------------------------------------------
__global__ void k_avg(float* __restrict__ out) {
    __shared__ float red[256];
    int b = blockIdx.x;
    for (int j = 0; j < 4; j++) {
        float s = 0.f;
        for (int t = threadIdx.x; t < CT; t += 256)
            s += g_PATT[((size_t)b * CT + t) * 4 + j];
        red[threadIdx.x] = s;
        __syncthreads();
        for (int w = 128; w > 0; w >>= 1) {
            if (threadIdx.x < w) red[threadIdx.x] += red[threadIdx.x + w];
            __syncthreads();
        }
        if (threadIdx.x == 0)
            out[(size_t)CB * CC * CT + b * 4 + j] = red[0] * (1.0f / CT);
        __syncthreads();
    }
}

// ---------------------------------------------------------------------------
// Host launcher (graph-capturable: kernel launches only)
// ---------------------------------------------------------------------------
extern "C" void kernel_launch(void* const* d_in, const int* in_sizes, int n_in,
                              void* d_out, int out_size) {
    const float* x   = (const float*)d_in[0];
    const float* emb = (const float*)d_in[1];
    const float* w1  = (const float*)d_in[2];
    const float* b1  = (const float*)d_in[3];
    const float* wo  = (const float*)d_in[4];
    const float* bo  = (const float*)d_in[5];
    const float* wp  = (const float*)d_in[6];
    const float* bp  = (const float*)d_in[7];
    const float* wim = (const float*)d_in[8];
    const float* bim = (const float*)d_in[9];
    const float* w2  = (const float*)d_in[10];
    const float* b2  = (const float*)d_in[11];
    float* out = (float*)d_out;

    __half *xe, *qkv, *ctx, *w1h, *uh;
    float *bt;
    cudaGetSymbolAddress((void**)&xe,  g_XE);
    cudaGetSymbolAddress((void**)&qkv, g_QKV);
    cudaGetSymbolAddress((void**)&ctx, g_CTX);
    cudaGetSymbolAddress((void**)&w1h, g_W1h);
    cudaGetSymbolAddress((void**)&uh,  g_Uh);
    cudaGetSymbolAddress((void**)&bt,  g_BT);

    cudaFuncSetAttribute(k_tgemm<3, 8, true>,
                         cudaFuncAttributeMaxDynamicSharedMemorySize, SMEM_G);
    cudaFuncSetAttribute(k_tgemm<2, 16, false>,
                         cudaFuncAttributeMaxDynamicSharedMemorySize, SMEM_G);

    // K1: embed + snn stage1 + w1 cvt + bias1 (all independent)
    k_embed_pre<<<dim3(CT / 32, CC / 32, 37), dim3(32, 8)>>>(
        x, emb, w1, w2, wp, bp, wim, bim, bo);

    // K2: GEMM1 QKV (65536 x 1536, K=512) fp16 out; +1 grid row = sred stage1
    k_tgemm<3, 8, true><<<dim3(3 * CC / BN, NROW / BM + 1), 256, SMEM_G>>>(
        xe, CC, w1h, CC, b1, nullptr, qkv, 3 * CC);

    // K3: attention -> ctx fp16; +1024 blocks = snn stage2 (S@Wo)
    k_attn<<<NTOK / 2 + 1024, 256>>>(wo);

    // K4: reduce stage2 partials -> Uh; bias2 -> BT
    k_finish<<<2050, 256>>>(w2, b2);

    // K5: fused out_proj+phone/imu+output (32768 x 512, K=1024), transposed
    k_tgemm<2, 16, false><<<dim3(CC / BN, NTOK / BM), 256, SMEM_G>>>(
        ctx, 2 * CC, uh, 2 * CC, bt, out, nullptr, 0);

    // K6: avg_attention tail
    k_avg<<<CB, 256>>>(out);
}